// round 17
// baseline (speedup 1.0000x reference)
#include <cuda_runtime.h>
#include <cstdint>

#define R_ROWS 4194304
#define ROWS_PER_BLOCK 1024
#define NBLK (R_ROWS / ROWS_PER_BLOCK)   // 4096
#define THREADS 256
#define ITEMS 4                          // rows per thread (blocked -> stable order)
#define TILE_BYTES (ROWS_PER_BLOCK * 6 * 4)   // 24576

#define N5 (R_ROWS * 5u)                 // 20971520 floats (rois)
#define N6 (R_ROWS * 6u)                 // 25165824 floats (rois_full)

// staging layout inside the shared buffer (floats):
//   [0, 6144)        : input tile, then reused for compacted B rows (cntB*6)
//   [6144, 11264)    : compacted A rows (cntA*5)
#define STAGE_FLOATS 11264               // 45056 bytes

// Decoupled-lookback state: one u64 per tile.
//   bits [62,64): 0 = invalid, 1 = aggregate ready, 2 = inclusive prefix ready
//   bits [24,48): count A    bits [0,24): count B   (totals <= 2^22, no carry)
#define FLAG_AGG (1ull << 62)
#define FLAG_PRE (2ull << 62)
#define PAYLOAD  ((1ull << 48) - 1ull)

__device__ unsigned long long g_state[NBLK];   // zero at load; reset by fill_kernel
__device__ int g_tot[2];

__device__ __forceinline__ uint32_t smem_u32(const void* p) {
    uint32_t a;
    asm("{ .reg .u64 t; cvta.to.shared.u64 t, %1; cvt.u32.u64 %0, t; }" : "=r"(a) : "l"(p));
    return a;
}

// ---------------------------------------------------------------------------
// Single pass: bulk-copy tile to SMEM, predicate, intra-block scan, early AGG
// publish, SMEM compaction, BLOCK-WIDE (256-window) decoupled lookback,
// streaming coalesced write-out of the two contiguous ranges.
// ---------------------------------------------------------------------------
__global__ __launch_bounds__(THREADS) void fused_kernel(const float* __restrict__ det,
                                                        float* __restrict__ out) {
    __shared__ alignas(128) float s_stage[STAGE_FLOATS];   // 44 KB (tile + staging)
    __shared__ alignas(8) unsigned long long s_mbar;
    __shared__ int wsum[THREADS / 32];
    __shared__ int s_agg;
    __shared__ unsigned long long s_excl;
    __shared__ unsigned s_wpm[THREADS / 32];
    __shared__ unsigned long long s_wpart[THREADS / 32];
    __shared__ unsigned long long s_wfull[THREADS / 32];
    __shared__ int s_done;

    const int blk = blockIdx.x;
    const uint32_t mbar = smem_u32(&s_mbar);
    const uint32_t sdst = smem_u32(s_stage);

    if (threadIdx.x == 0) {
        asm volatile("mbarrier.init.shared.b64 [%0], %1;" :: "r"(mbar), "r"(1) : "memory");
        asm volatile("mbarrier.arrive.expect_tx.shared.b64 _, [%0], %1;"
                     :: "r"(mbar), "r"((unsigned)TILE_BYTES) : "memory");
        const char* gsrc = (const char*)det + (size_t)blk * TILE_BYTES;
        asm volatile("cp.async.bulk.shared::cta.global.mbarrier::complete_tx::bytes "
                     "[%0], [%1], %2, [%3];"
                     :: "r"(sdst), "l"(gsrc), "r"((unsigned)TILE_BYTES), "r"(mbar)
                     : "memory");
    }
    __syncthreads();
    {   // wait for bulk copy (phase 0; fresh smem barrier each block)
        uint32_t done;
        asm volatile("{\n\t.reg .pred p;\n\t"
                     "mbarrier.try_wait.parity.acquire.cta.shared::cta.b64 p, [%1], %2;\n\t"
                     "selp.b32 %0, 1, 0, p;\n\t}"
                     : "=r"(done) : "r"(mbar), "r"(0u) : "memory");
        if (!done) {
            asm volatile("{\n\t.reg .pred P1;\n\t"
                         "WL_%=:\n\t"
                         "mbarrier.try_wait.parity.acquire.cta.shared::cta.b64 P1, [%0], %1, 0x989680;\n\t"
                         "@P1 bra.uni WD_%=;\n\t"
                         "bra.uni WL_%=;\n\t"
                         "WD_%=:\n\t}"
                         :: "r"(mbar), "r"(0u) : "memory");
        }
    }

    const float* sr = s_stage;
    const int r0 = threadIdx.x * ITEMS;

    float2 vrow[ITEMS][3];
    bool pa[ITEMS], pb[ITEMS];
    int cA = 0, cB = 0;
    #pragma unroll
    for (int j = 0; j < ITEMS; j++) {
        const float2* rp = (const float2*)(sr + (r0 + j) * 6);
        vrow[j][0] = rp[0];
        vrow[j][1] = rp[1];
        vrow[j][2] = rp[2];
        bool b = (vrow[j][2].y >= 0.35f);          // score
        bool a = b && (vrow[j][0].x == 0.0f);      // class id
        pa[j] = a; pb[j] = b;
        cA += a; cB += b;
    }

    // intra-block scan of packed (cntA<<16 | cntB)
    int packed = (cA << 16) | cB;
    int incp = packed;
    const int lane = threadIdx.x & 31, w = threadIdx.x >> 5;
    #pragma unroll
    for (int d = 1; d < 32; d <<= 1) {
        int o = __shfl_up_sync(0xffffffffu, incp, d);
        if (lane >= d) incp += o;
    }
    if (lane == 31) wsum[w] = incp;
    __syncthreads();   // input tile fully consumed; wsum ready

    volatile unsigned long long* st = (volatile unsigned long long*)g_state;

    // ---- thread 0: publish aggregate EARLY (shortens successors' lookback) ----
    unsigned long long agg64 = 0;   // thread-0 only
    if (threadIdx.x == 0) {
        int aggp = 0;
        #pragma unroll
        for (int i = 0; i < THREADS / 32; i++) aggp += wsum[i];
        s_agg = aggp;
        agg64 = ((unsigned long long)(unsigned)(aggp >> 16) << 24) |
                (unsigned long long)(unsigned)(aggp & 0xffff);
        if (blk == 0) {
            s_excl = 0ull;
            st[0] = FLAG_PRE | agg64;
        } else {
            st[blk] = FLAG_AGG | agg64;
        }
    }

    // intra-block exclusive prefix for this thread
    int wbase = 0;
    #pragma unroll
    for (int i = 0; i < THREADS / 32; i++)
        if (i < w) wbase += wsum[i];
    const int exc = wbase + incp - packed;

    // ---- compact into SMEM staging (input tile is dead now) ----
    {
        int tB = exc & 0xffff;
        int tA = exc >> 16;
        float* sB = s_stage;
        float* sA = s_stage + 6144;
        #pragma unroll
        for (int j = 0; j < ITEMS; j++) {
            if (pb[j]) {
                float* o = sB + tB * 6;
                o[0] = vrow[j][0].x; o[1] = vrow[j][0].y;
                o[2] = vrow[j][1].x; o[3] = vrow[j][1].y;
                o[4] = vrow[j][2].x; o[5] = vrow[j][2].y;
                tB++;
            }
            if (pa[j]) {
                float* o = sA + tA * 5;
                o[0] = 0.0f;
                o[1] = vrow[j][0].y;
                o[2] = vrow[j][1].x; o[3] = vrow[j][1].y;
                o[4] = vrow[j][2].x;
                tA++;
            }
        }
    }
    __syncthreads();   // staging complete; s_agg (and blk0 s_excl) visible

    // ---- BLOCK-WIDE lookback: 256 predecessors per window ----
    if (blk > 0) {
        unsigned long long run = 0;   // thread-0 only
        int base = blk - 1;
        for (;;) {
            const int idx = base - (int)threadIdx.x;
            unsigned long long s = FLAG_PRE;          // idx < 0 => prefix 0
            if (idx >= 0) {
                s = st[idx];
                while ((s >> 62) == 0ull) { __nanosleep(40); s = st[idx]; }
            }
            const bool pre = (idx < 0) || ((s >> 62) == 2ull);
            const unsigned pm = __ballot_sync(0xffffffffu, pre);
            const unsigned long long pay = s & PAYLOAD;
            unsigned long long full = pay;
            #pragma unroll
            for (int d = 16; d > 0; d >>= 1)
                full += __shfl_xor_sync(0xffffffffu, full, d);
            unsigned long long part = full;
            if (pm) {
                const int leader = __ffs(pm) - 1;     // nearest PRE in this warp
                unsigned long long v = (lane <= leader) ? pay : 0ull;
                #pragma unroll
                for (int d = 16; d > 0; d >>= 1)
                    v += __shfl_xor_sync(0xffffffffu, v, d);
                part = v;
            }
            if (lane == 0) { s_wpm[w] = pm; s_wpart[w] = part; s_wfull[w] = full; }
            __syncthreads();
            if (threadIdx.x == 0) {
                unsigned long long tot = 0; int found = 0;
                #pragma unroll
                for (int i = 0; i < THREADS / 32; i++) {
                    if (s_wpm[i]) { tot += s_wpart[i]; found = 1; break; }
                    tot += s_wfull[i];
                }
                s_done = found;
                if (found) {
                    const unsigned long long excl = run + tot;
                    s_excl = excl;
                    const unsigned long long inc = excl + agg64;
                    st[blk] = FLAG_PRE | inc;
                    if (blk == NBLK - 1) {
                        g_tot[0] = (int)((inc >> 24) & 0xffffffull);
                        g_tot[1] = (int)(inc & 0xffffffull);
                    }
                } else {
                    run += tot;
                }
            }
            __syncthreads();
            if (s_done) break;
            base -= THREADS;
        }
    }

    // ---- stream contiguous ranges to global (fully coalesced) ----
    const unsigned long long excl = s_excl;
    const int aggp  = s_agg;
    const int cntB  = aggp & 0xffff;
    const int cntA  = aggp >> 16;
    const int gB    = (int)(excl & 0xffffffull);
    const int gA    = (int)((excl >> 24) & 0xffffffull);

    {
        // B rows: 24B stride -> destination always 8B aligned; use float2
        float2* dstB2 = (float2*)(out + (size_t)N5 + (size_t)gB * 6);
        const float2* sB2 = (const float2*)s_stage;
        const int nB2 = cntB * 3;
        for (int i = threadIdx.x; i < nB2; i += THREADS) dstB2[i] = sB2[i];

        float* dstA = out + (size_t)gA * 5;
        const float* sA = s_stage + 6144;
        const int nA = cntA * 5;
        for (int i = threadIdx.x; i < nA; i += THREADS) dstA[i] = sA[i];
    }
}

// ---------------------------------------------------------------------------
// Fill: persistent grid-stride over TAIL QUADS ONLY + reset lookback state
// for the next graph replay (runs after fused_kernel, so this is safe).
// ---------------------------------------------------------------------------
#define FILL_BLOCKS 1184   // 8 blocks/SM x 148 SMs -> single wave
__global__ __launch_bounds__(256) void fill_kernel(float* __restrict__ out) {
    const unsigned tid = blockIdx.x * 256u + threadIdx.x;
    const unsigned stride = gridDim.x * 256u;

    if (tid < NBLK) g_state[tid] = 0ull;          // reset for next replay

    const int nA = g_tot[0];
    const int nB = g_tot[1];
    const unsigned a0 = (unsigned)nA * 5u;          // first tail element (A)
    const unsigned b0 = N5 + (unsigned)nB * 6u;     // first tail element (B)
    const unsigned aq  = a0 >> 2;
    const unsigned bq  = b0 >> 2;
    const unsigned aqe = N5 >> 2;
    const unsigned bqe = (N5 + N6) >> 2;

    float4* o4 = (float4*)out;
    const float4 z4 = make_float4(0.f, 0.f, 0.f, 0.f);

    for (unsigned i = aq + tid; i < aqe; i += stride) {
        if (i != aq || (a0 & 3u) == 0u) {
            o4[i] = z4;
        } else {
            #pragma unroll
            for (unsigned k = 0; k < 4; k++) {
                unsigned e = i * 4u + k;
                if (e >= a0) out[e] = 0.0f;
            }
        }
    }
    for (unsigned i = bq + tid; i < bqe; i += stride) {
        if (i != bq || (b0 & 3u) == 0u) {
            o4[i] = z4;
        } else {
            #pragma unroll
            for (unsigned k = 0; k < 4; k++) {
                unsigned e = i * 4u + k;
                if (e >= b0) out[e] = 0.0f;
            }
        }
    }
    if (tid == 0) {
        out[N5 + N6]      = (float)g_tot[0];
        out[N5 + N6 + 1u] = (float)g_tot[1];
    }
}

extern "C" void kernel_launch(void* const* d_in, const int* in_sizes, int n_in,
                              void* d_out, int out_size) {
    const float* det = (const float*)d_in[0];
    float* out = (float*)d_out;

    fused_kernel<<<NBLK, THREADS>>>(det, out);
    fill_kernel<<<FILL_BLOCKS, 256>>>(out);
}